// round 1
// baseline (speedup 1.0000x reference)
#include <cuda_runtime.h>

#define FULL 0xffffffffu

constexpr int   N_SAMP = 64;
constexpr int   RAYS_TOTAL = 4 * 64 * 64;   // 16384
constexpr float NEARF = 2.0f, FARF = 6.0f;
constexpr int   RPB = 8;                    // rays (warps) per block

// Evaluate the tiny MLP at TWO points, sharing all weight loads.
// h = relu(p @ W1 + b1); out = h @ W2 + b2; sigma = out0; rgb = sigmoid(out1..3)
__device__ __forceinline__ void field_eval2(
    float px0, float py0, float pz0,
    float px1, float py1, float pz1,
    const float4* __restrict__ w1a, const float4* __restrict__ w1b,
    const float4* __restrict__ w1c, const float4* __restrict__ bb1,
    const float4* __restrict__ w2,  const float*  __restrict__ b2s,
    float& sg0, float& r0, float& g0, float& b0,
    float& sg1, float& r1, float& g1, float& b1)
{
    float o00 = b2s[0], o01 = b2s[1], o02 = b2s[2], o03 = b2s[3];
    float o10 = b2s[0], o11 = b2s[1], o12 = b2s[2], o13 = b2s[3];
    #pragma unroll
    for (int q = 0; q < 16; ++q) {
        float4 a = w1a[q], b = w1b[q], c = w1c[q], d = bb1[q];
        {
            float h0 = fmaf(px0, a.x, fmaf(py0, b.x, fmaf(pz0, c.x, d.x))); h0 = fmaxf(h0, 0.f);
            float h1 = fmaf(px1, a.x, fmaf(py1, b.x, fmaf(pz1, c.x, d.x))); h1 = fmaxf(h1, 0.f);
            float4 v = w2[4 * q + 0];
            o00 = fmaf(h0, v.x, o00); o01 = fmaf(h0, v.y, o01); o02 = fmaf(h0, v.z, o02); o03 = fmaf(h0, v.w, o03);
            o10 = fmaf(h1, v.x, o10); o11 = fmaf(h1, v.y, o11); o12 = fmaf(h1, v.z, o12); o13 = fmaf(h1, v.w, o13);
        }
        {
            float h0 = fmaf(px0, a.y, fmaf(py0, b.y, fmaf(pz0, c.y, d.y))); h0 = fmaxf(h0, 0.f);
            float h1 = fmaf(px1, a.y, fmaf(py1, b.y, fmaf(pz1, c.y, d.y))); h1 = fmaxf(h1, 0.f);
            float4 v = w2[4 * q + 1];
            o00 = fmaf(h0, v.x, o00); o01 = fmaf(h0, v.y, o01); o02 = fmaf(h0, v.z, o02); o03 = fmaf(h0, v.w, o03);
            o10 = fmaf(h1, v.x, o10); o11 = fmaf(h1, v.y, o11); o12 = fmaf(h1, v.z, o12); o13 = fmaf(h1, v.w, o13);
        }
        {
            float h0 = fmaf(px0, a.z, fmaf(py0, b.z, fmaf(pz0, c.z, d.z))); h0 = fmaxf(h0, 0.f);
            float h1 = fmaf(px1, a.z, fmaf(py1, b.z, fmaf(pz1, c.z, d.z))); h1 = fmaxf(h1, 0.f);
            float4 v = w2[4 * q + 2];
            o00 = fmaf(h0, v.x, o00); o01 = fmaf(h0, v.y, o01); o02 = fmaf(h0, v.z, o02); o03 = fmaf(h0, v.w, o03);
            o10 = fmaf(h1, v.x, o10); o11 = fmaf(h1, v.y, o11); o12 = fmaf(h1, v.z, o12); o13 = fmaf(h1, v.w, o13);
        }
        {
            float h0 = fmaf(px0, a.w, fmaf(py0, b.w, fmaf(pz0, c.w, d.w))); h0 = fmaxf(h0, 0.f);
            float h1 = fmaf(px1, a.w, fmaf(py1, b.w, fmaf(pz1, c.w, d.w))); h1 = fmaxf(h1, 0.f);
            float4 v = w2[4 * q + 3];
            o00 = fmaf(h0, v.x, o00); o01 = fmaf(h0, v.y, o01); o02 = fmaf(h0, v.z, o02); o03 = fmaf(h0, v.w, o03);
            o10 = fmaf(h1, v.x, o10); o11 = fmaf(h1, v.y, o11); o12 = fmaf(h1, v.z, o12); o13 = fmaf(h1, v.w, o13);
        }
    }
    sg0 = o00;
    r0 = 1.f / (1.f + expf(-o01));
    g0 = 1.f / (1.f + expf(-o02));
    b0 = 1.f / (1.f + expf(-o03));
    sg1 = o10;
    r1 = 1.f / (1.f + expf(-o11));
    g1 = 1.f / (1.f + expf(-o12));
    b1 = 1.f / (1.f + expf(-o13));
}

__global__ void __launch_bounds__(RPB * 32)
nerf_kernel(const float* __restrict__ ro,   const float* __restrict__ rdi,
            const float* __restrict__ tform, const float* __restrict__ noise,
            const float* __restrict__ usmp,
            const float* __restrict__ gW1, const float* __restrict__ gb1,
            const float* __restrict__ gW2, const float* __restrict__ gb2,
            float* __restrict__ orgb, float* __restrict__ odep, float* __restrict__ omsk)
{
    __shared__ float4 sW1a[16], sW1b[16], sW1c[16], sB1[16], sW2[64];
    __shared__ float  sB2[4];
    __shared__ float  sZ [RPB][128];   // z values (unsorted, then sorted in place)
    __shared__ float  sSg[RPB][128];   // cdf scratch (0..62), then sorted sigma
    __shared__ float  sC [RPB][384];   // sorted rgb
    __shared__ float  sWt[RPB][64];    // coarse compositing weights

    const int tid = threadIdx.x;
    if (tid < 64) {
        ((float*)sW1a)[tid] = gW1[tid];
        ((float*)sW1b)[tid] = gW1[64 + tid];
        ((float*)sW1c)[tid] = gW1[128 + tid];
        ((float*)sB1)[tid]  = gb1[tid];
    }
    ((float*)sW2)[tid] = gW2[tid];          // blockDim == 256 == |W2|
    if (tid < 4) sB2[tid] = gb2[tid];
    __syncthreads();

    const int wrp = tid >> 5, lane = tid & 31;
    const int ray = blockIdx.x * RPB + wrp;
    float* zw  = sZ[wrp];
    float* sgw = sSg[wrp];
    float* cw  = sC[wrp];
    float* wtw = sWt[wrp];

    const int bidx = ray >> 12;   // H*W = 4096 rays per batch

    const float ox = ro[ray * 3 + 0], oy = ro[ray * 3 + 1], oz = ro[ray * 3 + 2];
    float dx = rdi[ray * 3 + 0], dy = rdi[ray * 3 + 1], dz = rdi[ray * 3 + 2];
    const float rinvn = rsqrtf(dx * dx + dy * dy + dz * dz);
    dx *= rinvn; dy *= rinvn; dz *= rinvn;

    // -------- coarse stratified z --------
    const float* nz = noise + ray * N_SAMP;
    const int i0 = 2 * lane, i1 = i0 + 1;
    const float z0 = NEARF + (FARF - NEARF) * (((float)i0 + nz[i0]) * (1.f / 64.f));
    const float z1 = NEARF + (FARF - NEARF) * (((float)i1 + nz[i1]) * (1.f / 64.f));
    zw[i0] = z0; zw[i1] = z1;
    __syncwarp();

    // -------- coarse MLP --------
    float sg0, cr0, cg0, cb0, sg1, cr1, cg1, cb1;
    field_eval2(fmaf(dx, z0, ox), fmaf(dy, z0, oy), fmaf(dz, z0, oz),
                fmaf(dx, z1, ox), fmaf(dy, z1, oy), fmaf(dz, z1, oz),
                sW1a, sW1b, sW1c, sB1, sW2, sB2,
                sg0, cr0, cg0, cb0, sg1, cr1, cg1, cb1);

    // -------- coarse compositing weights (warp multiplicative scan) --------
    const float d0 = z1 - z0;
    const float z2 = zw[(i1 + 1) & 127];
    const float d1 = (lane == 31) ? 1e10f : (z2 - z1);
    const float e0 = expf(-fmaxf(sg0, 0.f) * d0);
    const float e1 = expf(-fmaxf(sg1, 0.f) * d1);
    const float a0 = 1.f - e0, a1 = 1.f - e1;
    const float m0 = 1.f - a0 + 1e-10f, m1 = 1.f - a1 + 1e-10f;
    {
        float v = m0 * m1;
        #pragma unroll
        for (int off = 1; off < 32; off <<= 1) {
            float t = __shfl_up_sync(FULL, v, off);
            if (lane >= off) v *= t;
        }
        float ex = __shfl_up_sync(FULL, v, 1);
        if (lane == 0) ex = 1.f;
        wtw[i0] = a0 * ex;
        wtw[i1] = a1 * ex * m0;
    }
    __syncwarp();

    // -------- pooled pdf -> cdf (62 weights, 63-entry cdf in sgw[0..62]) --------
    {
        float s1 = 0.f, s2 = 0.f;
        if (lane < 31) {
            const int ii = 2 * lane + 1;
            const float wm = wtw[ii - 1], wc = wtw[ii], wp = wtw[ii + 1], wq = wtw[ii + 2];
            s1 = 0.5f * (fmaxf(wm, wc) + fmaxf(wc, wp)) + 0.01f;
            s2 = 0.5f * (fmaxf(wc, wp) + fmaxf(wp, wq)) + 0.01f;
        }
        const float pr = s1 + s2;
        float v = pr;
        #pragma unroll
        for (int off = 1; off < 32; off <<= 1) {
            float t = __shfl_up_sync(FULL, v, off);
            if (lane >= off) v += t;
        }
        const float tot = __shfl_sync(FULL, v, 30);
        const float rv = 1.f / tot;
        const float ex = v - pr;
        if (lane == 0) sgw[0] = 0.f;
        if (lane < 31) {
            sgw[2 * lane + 1] = (ex + s1) * rv;
            sgw[2 * lane + 2] = v * rv;
        }
    }
    __syncwarp();

    // -------- inverse-CDF fine samples (2 per lane) --------
    const float* uu = usmp + ray * N_SAMP;
    float zs0 = 0.f, zs1 = 0.f;
    #pragma unroll
    for (int k = 0; k < 2; ++k) {
        const float u = uu[lane + 32 * k];
        int lo = 0, hi = 63;                       // searchsorted(cdf[0..62], u, right)
        while (lo < hi) {
            const int mid = (lo + hi) >> 1;
            if (sgw[mid] <= u) lo = mid + 1; else hi = mid;
        }
        const int below = lo - 1;                  // in [0,62]
        const int above = lo < 62 ? lo : 62;
        const float cbv = sgw[below], cav = sgw[above];
        float den = cav - cbv;
        if (den < 1e-5f) den = 1.f;
        const float t  = (u - cbv) / den;
        const float bb = 0.5f * (zw[below] + zw[below + 1]);
        const float ba = 0.5f * (zw[above] + zw[above + 1]);
        const float zz = fmaf(t, ba - bb, bb);
        if (k == 0) zs0 = zz; else zs1 = zz;
    }
    __syncwarp();                                  // all cdf reads done before reuse
    zw[64 + lane] = zs0;
    zw[96 + lane] = zs1;

    // -------- fine MLP --------
    float fs0, fr0, fg0, fb0, fs1, fr1, fg1, fb1;
    field_eval2(fmaf(dx, zs0, ox), fmaf(dy, zs0, oy), fmaf(dz, zs0, oz),
                fmaf(dx, zs1, ox), fmaf(dy, zs1, oy), fmaf(dz, zs1, oz),
                sW1a, sW1b, sW1c, sB1, sW2, sB2,
                fs0, fr0, fg0, fb0, fs1, fr1, fg1, fb1);
    __syncwarp();                                  // all 128 z in shared

    // -------- stable rank (merged argsort) --------
    const int g2 = 64 + lane, g3 = 96 + lane;
    int r0 = 0, r1 = 0, r2 = 0, r3 = 0;
    #pragma unroll 4
    for (int j = 0; j < 128; ++j) {
        const float zj = zw[j];
        r0 += (zj < z0)  ? 1 : ((zj == z0  && j < i0) ? 1 : 0);
        r1 += (zj < z1)  ? 1 : ((zj == z1  && j < i1) ? 1 : 0);
        r2 += (zj < zs0) ? 1 : ((zj == zs0 && j < g2) ? 1 : 0);
        r3 += (zj < zs1) ? 1 : ((zj == zs1 && j < g3) ? 1 : 0);
    }
    __syncwarp();                                  // ranks done before scatter

    zw[r0] = z0;  sgw[r0] = sg0; cw[3 * r0] = cr0; cw[3 * r0 + 1] = cg0; cw[3 * r0 + 2] = cb0;
    zw[r1] = z1;  sgw[r1] = sg1; cw[3 * r1] = cr1; cw[3 * r1 + 1] = cg1; cw[3 * r1 + 2] = cb1;
    zw[r2] = zs0; sgw[r2] = fs0; cw[3 * r2] = fr0; cw[3 * r2 + 1] = fg0; cw[3 * r2 + 2] = fb0;
    zw[r3] = zs1; sgw[r3] = fs1; cw[3 * r3] = fr1; cw[3 * r3 + 1] = fg1; cw[3 * r3 + 2] = fb1;
    __syncwarp();

    // -------- final compositing over 128 sorted samples (4 per lane) --------
    const int p = 4 * lane;
    const float za = zw[p], zb = zw[p + 1], zc = zw[p + 2], zd = zw[p + 3];
    const float zn = (lane < 31) ? zw[p + 4] : 0.f;
    const float sa = sgw[p], sb = sgw[p + 1], sc = sgw[p + 2], sd = sgw[p + 3];
    const float dda = zb - za, ddb = zc - zb, ddc = zd - zc;
    const float ddd = (lane == 31) ? 1e10f : (zn - zd);
    const float ea2 = expf(-fmaxf(sa, 0.f) * dda);
    const float eb2 = expf(-fmaxf(sb, 0.f) * ddb);
    const float ec2 = expf(-fmaxf(sc, 0.f) * ddc);
    const float ed2 = expf(-fmaxf(sd, 0.f) * ddd);
    const float aa = 1.f - ea2, ab = 1.f - eb2, ac = 1.f - ec2, ad = 1.f - ed2;
    const float ma = 1.f - aa + 1e-10f, mb = 1.f - ab + 1e-10f;
    const float mc = 1.f - ac + 1e-10f, md = 1.f - ad + 1e-10f;
    const float q0 = ma, q1 = ma * mb, q2 = q1 * mc, q3 = q2 * md;
    float v = q3;
    #pragma unroll
    for (int off = 1; off < 32; off <<= 1) {
        float t = __shfl_up_sync(FULL, v, off);
        if (lane >= off) v *= t;
    }
    float E = __shfl_up_sync(FULL, v, 1);
    if (lane == 0) E = 1.f;
    const float wA = aa * E, wB = ab * E * q0, wC = ac * E * q1, wD = ad * E * q2;

    float SW = wA + wB + wC + wD;
    float SZ = wA * za + wB * zb + wC * zc + wD * zd;
    float SR = wA * cw[3 * p]     + wB * cw[3 * (p + 1)]     + wC * cw[3 * (p + 2)]     + wD * cw[3 * (p + 3)];
    float SG = wA * cw[3 * p + 1] + wB * cw[3 * (p + 1) + 1] + wC * cw[3 * (p + 2) + 1] + wD * cw[3 * (p + 3) + 1];
    float SB = wA * cw[3 * p + 2] + wB * cw[3 * (p + 1) + 2] + wC * cw[3 * (p + 2) + 2] + wD * cw[3 * (p + 3) + 2];

    #pragma unroll
    for (int off = 16; off; off >>= 1) {
        SW += __shfl_xor_sync(FULL, SW, off);
        SZ += __shfl_xor_sync(FULL, SZ, off);
        SR += __shfl_xor_sync(FULL, SR, off);
        SG += __shfl_xor_sync(FULL, SG, off);
        SB += __shfl_xor_sync(FULL, SB, off);
    }

    if (lane == 0) {
        orgb[ray * 3 + 0] = SR;
        orgb[ray * 3 + 1] = SG;
        orgb[ray * 3 + 2] = SB;
        const float* Tm = tform + bidx * 16;
        const float vz = dx * Tm[2] + dy * Tm[6] + dz * Tm[10];   // (rd @ R)[...,2]
        odep[ray] = -vz * SZ;
        omsk[ray] = SW;
    }
}

extern "C" void kernel_launch(void* const* d_in, const int* in_sizes, int n_in,
                              void* d_out, int out_size)
{
    const float* ro    = (const float*)d_in[0];  // ray_origins      [B,H,W,3]
    const float* rdi   = (const float*)d_in[1];  // ray_directions   [B,H,W,3]
    const float* tform = (const float*)d_in[2];  // tform_cam2world  [B,4,4]
    const float* noise = (const float*)d_in[3];  // depth_noise      [B,H,W,N]
    const float* usmp  = (const float*)d_in[4];  // u_samples        [B,H,W,N]
    const float* W1    = (const float*)d_in[5];  // [3,64]
    const float* b1    = (const float*)d_in[6];  // [64]
    const float* W2    = (const float*)d_in[7];  // [64,4]
    const float* b2    = (const float*)d_in[8];  // [4]

    float* out = (float*)d_out;
    float* orgb = out;                     // [B,H,W,3] = 49152
    float* odep = out + RAYS_TOTAL * 3;    // [B,H,W]   = 16384
    float* omsk = odep + RAYS_TOTAL;       // [B,H,W]   = 16384

    dim3 grid(RAYS_TOTAL / RPB);           // 2048 blocks
    dim3 block(RPB * 32);                  // 256 threads, 1 warp per ray
    nerf_kernel<<<grid, block>>>(ro, rdi, tform, noise, usmp, W1, b1, W2, b2,
                                 orgb, odep, omsk);
}

// round 2
// speedup vs baseline: 2.1245x; 2.1245x over previous
#include <cuda_runtime.h>

#define FULL 0xffffffffu
typedef unsigned long long ull;

constexpr int   N_SAMP = 64;
constexpr int   RAYS_TOTAL = 4 * 64 * 64;   // 16384
constexpr float NEARF = 2.0f, FARF = 6.0f;
constexpr int   RPB = 8;                    // rays (warps) per block

__device__ __forceinline__ ull pack2(float lo, float hi) {
    ull r; asm("mov.b64 %0,{%1,%2};" : "=l"(r) : "f"(lo), "f"(hi)); return r;
}
__device__ __forceinline__ void unpack2(ull v, float& lo, float& hi) {
    asm("mov.b64 {%0,%1},%2;" : "=f"(lo), "=f"(hi) : "l"(v));
}
__device__ __forceinline__ ull fma2(ull a, ull b, ull c) {
    ull d; asm("fma.rn.f32x2 %0,%1,%2,%3;" : "=l"(d) : "l"(a), "l"(b), "l"(c)); return d;
}

// # elements < x in sorted a[0..63]
__device__ __forceinline__ int count_lt(const float* __restrict__ a, float x) {
    int lo = 0, hi = 64;
    #pragma unroll
    for (int it = 0; it < 7; ++it) {
        if (lo < hi) { int m = (lo + hi) >> 1; if (a[m] < x) lo = m + 1; else hi = m; }
    }
    return lo;
}
// # elements <= x in sorted a[0..63]
__device__ __forceinline__ int count_le(const float* __restrict__ a, float x) {
    int lo = 0, hi = 64;
    #pragma unroll
    for (int it = 0; it < 7; ++it) {
        if (lo < hi) { int m = (lo + hi) >> 1; if (a[m] <= x) lo = m + 1; else hi = m; }
    }
    return lo;
}

// Tiny MLP at TWO points, f32x2-packed across hidden-unit pairs and output pairs.
// W1 arrays: ulonglong2[q] = units {4q,4q+1} (.x) and {4q+2,4q+3} (.y) packed pairs.
// w2[u] (ulonglong2): .x = {W2[u][0],W2[u][1]}, .y = {W2[u][2],W2[u][3]}.
__device__ __forceinline__ void field_eval2(
    float px0, float py0, float pz0,
    float px1, float py1, float pz1,
    const ulonglong2* __restrict__ w1a, const ulonglong2* __restrict__ w1b,
    const ulonglong2* __restrict__ w1c, const ulonglong2* __restrict__ bb1,
    const ulonglong2* __restrict__ w2, ull b2lo, ull b2hi,
    float& sg0, float& r0, float& g0, float& b0,
    float& sg1, float& r1, float& g1, float& b1)
{
    const ull X0 = pack2(px0, px0), Y0 = pack2(py0, py0), Z0 = pack2(pz0, pz0);
    const ull X1 = pack2(px1, px1), Y1 = pack2(py1, py1), Z1 = pack2(pz1, pz1);
    ull oA0 = b2lo, oB0 = b2hi, oA1 = b2lo, oB1 = b2hi;
    #pragma unroll
    for (int q = 0; q < 16; ++q) {
        const ulonglong2 A = w1a[q], Bw = w1b[q], C = w1c[q], D = bb1[q];
        const ull hP0a = fma2(X0, A.x, fma2(Y0, Bw.x, fma2(Z0, C.x, D.x)));
        const ull hP0b = fma2(X0, A.y, fma2(Y0, Bw.y, fma2(Z0, C.y, D.y)));
        const ull hP1a = fma2(X1, A.x, fma2(Y1, Bw.x, fma2(Z1, C.x, D.x)));
        const ull hP1b = fma2(X1, A.y, fma2(Y1, Bw.y, fma2(Z1, C.y, D.y)));
        float h00, h01, h02, h03, h10, h11, h12, h13;
        unpack2(hP0a, h00, h01); unpack2(hP0b, h02, h03);
        unpack2(hP1a, h10, h11); unpack2(hP1b, h12, h13);
        h00 = fmaxf(h00, 0.f); h01 = fmaxf(h01, 0.f); h02 = fmaxf(h02, 0.f); h03 = fmaxf(h03, 0.f);
        h10 = fmaxf(h10, 0.f); h11 = fmaxf(h11, 0.f); h12 = fmaxf(h12, 0.f); h13 = fmaxf(h13, 0.f);
        const ulonglong2 V0 = w2[4 * q + 0], V1 = w2[4 * q + 1];
        const ulonglong2 V2 = w2[4 * q + 2], V3 = w2[4 * q + 3];
        ull t;
        t = pack2(h00, h00); oA0 = fma2(t, V0.x, oA0); oB0 = fma2(t, V0.y, oB0);
        t = pack2(h10, h10); oA1 = fma2(t, V0.x, oA1); oB1 = fma2(t, V0.y, oB1);
        t = pack2(h01, h01); oA0 = fma2(t, V1.x, oA0); oB0 = fma2(t, V1.y, oB0);
        t = pack2(h11, h11); oA1 = fma2(t, V1.x, oA1); oB1 = fma2(t, V1.y, oB1);
        t = pack2(h02, h02); oA0 = fma2(t, V2.x, oA0); oB0 = fma2(t, V2.y, oB0);
        t = pack2(h12, h12); oA1 = fma2(t, V2.x, oA1); oB1 = fma2(t, V2.y, oB1);
        t = pack2(h03, h03); oA0 = fma2(t, V3.x, oA0); oB0 = fma2(t, V3.y, oB0);
        t = pack2(h13, h13); oA1 = fma2(t, V3.x, oA1); oB1 = fma2(t, V3.y, oB1);
    }
    float o00, o01, o02, o03, o10, o11, o12, o13;
    unpack2(oA0, o00, o01); unpack2(oB0, o02, o03);
    unpack2(oA1, o10, o11); unpack2(oB1, o12, o13);
    sg0 = o00;
    r0 = __fdividef(1.f, 1.f + __expf(-o01));
    g0 = __fdividef(1.f, 1.f + __expf(-o02));
    b0 = __fdividef(1.f, 1.f + __expf(-o03));
    sg1 = o10;
    r1 = __fdividef(1.f, 1.f + __expf(-o11));
    g1 = __fdividef(1.f, 1.f + __expf(-o12));
    b1 = __fdividef(1.f, 1.f + __expf(-o13));
}

__global__ void __launch_bounds__(RPB * 32)
nerf_kernel(const float* __restrict__ ro,   const float* __restrict__ rdi,
            const float* __restrict__ tform, const float* __restrict__ noise,
            const float* __restrict__ usmp,
            const float* __restrict__ gW1, const float* __restrict__ gb1,
            const float* __restrict__ gW2, const float* __restrict__ gb2,
            float* __restrict__ orgb, float* __restrict__ odep, float* __restrict__ omsk)
{
    __shared__ float4 sW1a[16], sW1b[16], sW1c[16], sB1[16], sW2[64];
    __shared__ float  sB2[4];
    __shared__ float  sZ [RPB][128];   // coarse z [0..63], then all-sorted z
    __shared__ float  sSg[RPB][128];   // cdf [0..62], sorted fine [64..127], then sorted sigma
    __shared__ float  sC [RPB][384];   // sorted rgb
    __shared__ float  sWt[RPB][64];    // coarse compositing weights

    const int tid = threadIdx.x;
    if (tid < 64) {
        ((float*)sW1a)[tid] = gW1[tid];
        ((float*)sW1b)[tid] = gW1[64 + tid];
        ((float*)sW1c)[tid] = gW1[128 + tid];
        ((float*)sB1)[tid]  = gb1[tid];
    }
    ((float*)sW2)[tid] = gW2[tid];
    if (tid < 4) sB2[tid] = gb2[tid];
    __syncthreads();

    const ulonglong2* w1a2 = (const ulonglong2*)sW1a;
    const ulonglong2* w1b2 = (const ulonglong2*)sW1b;
    const ulonglong2* w1c2 = (const ulonglong2*)sW1c;
    const ulonglong2* bb12 = (const ulonglong2*)sB1;
    const ulonglong2* w22  = (const ulonglong2*)sW2;
    const ull b2lo = pack2(sB2[0], sB2[1]);
    const ull b2hi = pack2(sB2[2], sB2[3]);

    const int wrp = tid >> 5, lane = tid & 31;
    const int ray = blockIdx.x * RPB + wrp;
    float* zw  = sZ[wrp];
    float* sgw = sSg[wrp];
    float* sf  = sgw + 64;     // sorted fine z
    float* cw  = sC[wrp];
    float* wtw = sWt[wrp];

    const int bidx = ray >> 12;

    const float ox = ro[ray * 3 + 0], oy = ro[ray * 3 + 1], oz = ro[ray * 3 + 2];
    float dx = rdi[ray * 3 + 0], dy = rdi[ray * 3 + 1], dz = rdi[ray * 3 + 2];
    const float rinvn = rsqrtf(dx * dx + dy * dy + dz * dz);
    dx *= rinvn; dy *= rinvn; dz *= rinvn;

    // -------- coarse stratified z (sorted by construction) --------
    const float* nz = noise + ray * N_SAMP;
    const int i0 = 2 * lane, i1 = i0 + 1;
    const float z0 = NEARF + (FARF - NEARF) * (((float)i0 + nz[i0]) * (1.f / 64.f));
    const float z1 = NEARF + (FARF - NEARF) * (((float)i1 + nz[i1]) * (1.f / 64.f));
    zw[i0] = z0; zw[i1] = z1;
    __syncwarp();

    // -------- coarse MLP --------
    float sg0, cr0, cg0, cb0, sg1, cr1, cg1, cb1;
    field_eval2(fmaf(dx, z0, ox), fmaf(dy, z0, oy), fmaf(dz, z0, oz),
                fmaf(dx, z1, ox), fmaf(dy, z1, oy), fmaf(dz, z1, oz),
                w1a2, w1b2, w1c2, bb12, w22, b2lo, b2hi,
                sg0, cr0, cg0, cb0, sg1, cr1, cg1, cb1);

    // -------- coarse compositing weights (warp multiplicative scan) --------
    const float d0 = z1 - z0;
    const float znx = (lane < 31) ? zw[i1 + 1] : 0.f;
    const float d1 = (lane == 31) ? 1e10f : (znx - z1);
    const float e0 = __expf(-fmaxf(sg0, 0.f) * d0);
    const float e1 = __expf(-fmaxf(sg1, 0.f) * d1);
    const float a0 = 1.f - e0, a1 = 1.f - e1;
    const float m0 = 1.f - a0 + 1e-10f, m1 = 1.f - a1 + 1e-10f;
    {
        float v = m0 * m1;
        #pragma unroll
        for (int off = 1; off < 32; off <<= 1) {
            float t = __shfl_up_sync(FULL, v, off);
            if (lane >= off) v *= t;
        }
        float ex = __shfl_up_sync(FULL, v, 1);
        if (lane == 0) ex = 1.f;
        wtw[i0] = a0 * ex;
        wtw[i1] = a1 * ex * m0;
    }
    __syncwarp();

    // -------- pooled pdf -> cdf (63 entries in sgw[0..62]) --------
    {
        float s1 = 0.f, s2 = 0.f;
        if (lane < 31) {
            const int ii = 2 * lane + 1;
            const float wm = wtw[ii - 1], wc = wtw[ii], wp = wtw[ii + 1], wq = wtw[ii + 2];
            s1 = 0.5f * (fmaxf(wm, wc) + fmaxf(wc, wp)) + 0.01f;
            s2 = 0.5f * (fmaxf(wc, wp) + fmaxf(wp, wq)) + 0.01f;
        }
        const float pr = s1 + s2;
        float v = pr;
        #pragma unroll
        for (int off = 1; off < 32; off <<= 1) {
            float t = __shfl_up_sync(FULL, v, off);
            if (lane >= off) v += t;
        }
        const float tot = __shfl_sync(FULL, v, 30);
        const float rv = __fdividef(1.f, tot);
        const float ex = v - pr;
        if (lane == 0) sgw[0] = 0.f;
        if (lane < 31) {
            sgw[2 * lane + 1] = (ex + s1) * rv;
            sgw[2 * lane + 2] = v * rv;
        }
    }
    __syncwarp();

    // -------- inverse-CDF fine samples (2 per lane, unsorted) --------
    const float* uu = usmp + ray * N_SAMP;
    float zs0 = 0.f, zs1 = 0.f;
    #pragma unroll
    for (int k = 0; k < 2; ++k) {
        const float u = uu[lane + 32 * k];
        int lo = 0, hi = 63;                       // searchsorted(cdf[0..62], u, right)
        while (lo < hi) {
            const int mid = (lo + hi) >> 1;
            if (sgw[mid] <= u) lo = mid + 1; else hi = mid;
        }
        const int below = lo - 1;
        const int above = lo < 62 ? lo : 62;
        const float cbv = sgw[below], cav = sgw[above];
        float den = cav - cbv;
        if (den < 1e-5f) den = 1.f;
        const float t  = __fdividef(u - cbv, den);
        const float bb = 0.5f * (zw[below] + zw[below + 1]);
        const float ba = 0.5f * (zw[above] + zw[above + 1]);
        const float zz = fmaf(t, ba - bb, bb);
        if (k == 0) zs0 = zz; else zs1 = zz;
    }

    // -------- bitonic sort of the 64 fine samples (registers + shfl) --------
    // element index e0 = lane, e1 = lane + 32
    float v0 = zs0, v1 = zs1;
    {
        const int e0l = lane, e1l = lane + 32;
        #pragma unroll
        for (int k = 2; k <= 64; k <<= 1) {
            #pragma unroll
            for (int j = k >> 1; j >= 1; j >>= 1) {
                if (j == 32) {
                    const float lo = fminf(v0, v1), hi = fmaxf(v0, v1);
                    v0 = lo; v1 = hi;
                } else {
                    const float t0 = __shfl_xor_sync(FULL, v0, j);
                    const bool keep0 = (((e0l & k) == 0) == ((e0l & j) == 0));
                    v0 = keep0 ? fminf(v0, t0) : fmaxf(v0, t0);
                    const float t1 = __shfl_xor_sync(FULL, v1, j);
                    const bool keep1 = (((e1l & k) == 0) == ((e1l & j) == 0));
                    v1 = keep1 ? fminf(v1, t1) : fmaxf(v1, t1);
                }
            }
        }
    }
    __syncwarp();                                  // cdf reads done before sf write
    sf[lane] = v0;
    sf[lane + 32] = v1;

    // -------- fine MLP at SORTED fine positions --------
    float fs0, fr0, fg0, fb0, fs1, fr1, fg1, fb1;
    field_eval2(fmaf(dx, v0, ox), fmaf(dy, v0, oy), fmaf(dz, v0, oz),
                fmaf(dx, v1, ox), fmaf(dy, v1, oy), fmaf(dz, v1, oz),
                w1a2, w1b2, w1c2, bb12, w22, b2lo, b2hi,
                fs0, fr0, fg0, fb0, fs1, fr1, fg1, fb1);
    __syncwarp();                                  // sf fully written

    // -------- merge ranks: coarse sorted x fine sorted --------
    const int r0 = i0 + count_lt(sf, z0);          // ties: coarse first
    const int r1 = i1 + count_lt(sf, z1);
    const int r2 = lane      + count_le(zw, v0);   // ties: fine after coarse
    const int r3 = lane + 32 + count_le(zw, v1);
    __syncwarp();                                  // all reads done before scatter

    zw[r0] = z0; sgw[r0] = sg0; cw[3 * r0] = cr0; cw[3 * r0 + 1] = cg0; cw[3 * r0 + 2] = cb0;
    zw[r1] = z1; sgw[r1] = sg1; cw[3 * r1] = cr1; cw[3 * r1 + 1] = cg1; cw[3 * r1 + 2] = cb1;
    zw[r2] = v0; sgw[r2] = fs0; cw[3 * r2] = fr0; cw[3 * r2 + 1] = fg0; cw[3 * r2 + 2] = fb0;
    zw[r3] = v1; sgw[r3] = fs1; cw[3 * r3] = fr1; cw[3 * r3 + 1] = fg1; cw[3 * r3 + 2] = fb1;
    __syncwarp();

    // -------- final compositing over 128 sorted samples (4 per lane) --------
    const int p = 4 * lane;
    const float za = zw[p], zb = zw[p + 1], zc = zw[p + 2], zd = zw[p + 3];
    const float zn = (lane < 31) ? zw[p + 4] : 0.f;
    const float sa = sgw[p], sb = sgw[p + 1], sc = sgw[p + 2], sd = sgw[p + 3];
    const float dda = zb - za, ddb = zc - zb, ddc = zd - zc;
    const float ddd = (lane == 31) ? 1e10f : (zn - zd);
    const float ea2 = __expf(-fmaxf(sa, 0.f) * dda);
    const float eb2 = __expf(-fmaxf(sb, 0.f) * ddb);
    const float ec2 = __expf(-fmaxf(sc, 0.f) * ddc);
    const float ed2 = __expf(-fmaxf(sd, 0.f) * ddd);
    const float aa = 1.f - ea2, ab = 1.f - eb2, ac = 1.f - ec2, ad = 1.f - ed2;
    const float ma = 1.f - aa + 1e-10f, mb = 1.f - ab + 1e-10f;
    const float mc = 1.f - ac + 1e-10f, md = 1.f - ad + 1e-10f;
    const float q0 = ma, q1 = ma * mb, q2 = q1 * mc, q3 = q2 * md;
    float v = q3;
    #pragma unroll
    for (int off = 1; off < 32; off <<= 1) {
        float t = __shfl_up_sync(FULL, v, off);
        if (lane >= off) v *= t;
    }
    float E = __shfl_up_sync(FULL, v, 1);
    if (lane == 0) E = 1.f;
    const float wA = aa * E, wB = ab * E * q0, wC = ac * E * q1, wD = ad * E * q2;

    float SW = wA + wB + wC + wD;
    float SZ = wA * za + wB * zb + wC * zc + wD * zd;
    float SR = wA * cw[3 * p]     + wB * cw[3 * (p + 1)]     + wC * cw[3 * (p + 2)]     + wD * cw[3 * (p + 3)];
    float SG = wA * cw[3 * p + 1] + wB * cw[3 * (p + 1) + 1] + wC * cw[3 * (p + 2) + 1] + wD * cw[3 * (p + 3) + 1];
    float SB = wA * cw[3 * p + 2] + wB * cw[3 * (p + 1) + 2] + wC * cw[3 * (p + 2) + 2] + wD * cw[3 * (p + 3) + 2];

    #pragma unroll
    for (int off = 16; off; off >>= 1) {
        SW += __shfl_xor_sync(FULL, SW, off);
        SZ += __shfl_xor_sync(FULL, SZ, off);
        SR += __shfl_xor_sync(FULL, SR, off);
        SG += __shfl_xor_sync(FULL, SG, off);
        SB += __shfl_xor_sync(FULL, SB, off);
    }

    if (lane == 0) {
        orgb[ray * 3 + 0] = SR;
        orgb[ray * 3 + 1] = SG;
        orgb[ray * 3 + 2] = SB;
        const float* Tm = tform + bidx * 16;
        const float vz = dx * Tm[2] + dy * Tm[6] + dz * Tm[10];
        odep[ray] = -vz * SZ;
        omsk[ray] = SW;
    }
}

extern "C" void kernel_launch(void* const* d_in, const int* in_sizes, int n_in,
                              void* d_out, int out_size)
{
    const float* ro    = (const float*)d_in[0];
    const float* rdi   = (const float*)d_in[1];
    const float* tform = (const float*)d_in[2];
    const float* noise = (const float*)d_in[3];
    const float* usmp  = (const float*)d_in[4];
    const float* W1    = (const float*)d_in[5];
    const float* b1    = (const float*)d_in[6];
    const float* W2    = (const float*)d_in[7];
    const float* b2    = (const float*)d_in[8];

    float* out = (float*)d_out;
    float* orgb = out;
    float* odep = out + RAYS_TOTAL * 3;
    float* omsk = odep + RAYS_TOTAL;

    dim3 grid(RAYS_TOTAL / RPB);
    dim3 block(RPB * 32);
    nerf_kernel<<<grid, block>>>(ro, rdi, tform, noise, usmp, W1, b1, W2, b2,
                                 orgb, odep, omsk);
}